// round 6
// baseline (speedup 1.0000x reference)
#include <cuda_runtime.h>

// Problem shape (fixed by setup_inputs): B=256, N=65536, half=32768.
#define NCOL     65536
#define HALF     32768
#define NROW_MAX 512
#define CHUNKS   16
#define CHUNK_C4 (HALF / 4 / CHUNKS)   // 512 float4 per chunk per half
#define BDIM     256
#define NITER    (CHUNK_C4 / BDIM)     // 2
#define NSEG4    (HALF / 4)            // 8192 4-element blocks per half

#define THRESH  0.01f
#define PENALTY 2.0f

// All zero-initialized at module load; every counter/enc value is reset to 0
// by its last reader, so graph replays see a clean state.
__device__ float    g_unit[NROW_MAX * CHUNKS];
__device__ float    g_rowsum[NROW_MAX];
__device__ int      g_encfr[NROW_MAX];   // atomicMax of (NSEG4 - c4); 0 = none
__device__ int      g_enclr[NROW_MAX];   // atomicMax of (c4 + 1);     0 = none
__device__ int      g_encfi[NROW_MAX];
__device__ int      g_encli[NROW_MAX];
__device__ unsigned g_rowcnt[NROW_MAX];
__device__ unsigned g_done = 0;

__global__ __launch_bounds__(BDIM, 6)
void loss_kernel(const float* __restrict__ pred,
                 const float* __restrict__ lab,
                 float* __restrict__ out,
                 int B)
{
    const int unit = blockIdx.x;
    const int row  = unit / CHUNKS;
    const int cnk  = unit % CHUNKS;
    const size_t rb = (size_t)row * NCOL;
    const int c4_0 = cnk * CHUNK_C4;          // base float4 index within half

    const float4* __restrict__ lr4 = (const float4*)(lab  + rb);
    const float4* __restrict__ li4 = (const float4*)(lab  + rb + HALF);
    const float4* __restrict__ pr4 = (const float4*)(pred + rb);
    const float4* __restrict__ pi4 = (const float4*)(pred + rb + HALF);

    const int tid  = threadIdx.x;
    const int lane = tid & 31;
    const int warp = tid >> 5;

    // ---- main pass: unweighted base loss + 4-granular min/max tracking ------
    float acc = 0.0f;
    int minr = INT_MAX, maxr = -1;
    int mini = INT_MAX, maxi = -1;

    #pragma unroll
    for (int it = 0; it < NITER; it++) {
        int c4 = c4_0 + tid + it * BDIM;
        float4 L  = lr4[c4];
        float4 Li = li4[c4];
        float4 P  = pr4[c4];
        float4 Pi = pi4[c4];

        float m_r = fmaxf(fmaxf(fabsf(L.x),  fabsf(L.y)),  fmaxf(fabsf(L.z),  fabsf(L.w)));
        float m_i = fmaxf(fmaxf(fabsf(Li.x), fabsf(Li.y)), fmaxf(fabsf(Li.z), fabsf(Li.w)));
        if (m_r > THRESH) { minr = min(minr, c4); maxr = max(maxr, c4); }
        if (m_i > THRESH) { mini = min(mini, c4); maxi = max(maxi, c4); }

        #pragma unroll
        for (int k = 0; k < 4; k++) {
            float lrx = (&L.x)[k],  lix = (&Li.x)[k];
            float prx = (&P.x)[k],  pix = (&Pi.x)[k];
            float dr = prx - lrx;
            float di = pix - lix;
            float dint = fmaf(pix, pix, prx * prx) - fmaf(lix, lix, lrx * lrx);
            acc = fmaf(dr, dr, acc);
            acc = fmaf(di, di, acc);
            acc = fmaf(50.0f * dint, dint, acc);
        }
    }

    // ---- CTA reduce: acc sum, min/max ---------------------------------------
    __shared__ float s_acc[BDIM / 32];
    __shared__ int   s_minr[BDIM / 32], s_maxr[BDIM / 32];
    __shared__ int   s_mini[BDIM / 32], s_maxi[BDIM / 32];
    __shared__ int   sh_fr, sh_lr, sh_fi, sh_li;
    __shared__ bool  s_last_row, s_last_all;

    #pragma unroll
    for (int off = 16; off > 0; off >>= 1) {
        acc += __shfl_xor_sync(0xFFFFFFFFu, acc, off);
        minr = min(minr, __shfl_xor_sync(0xFFFFFFFFu, minr, off));
        maxr = max(maxr, __shfl_xor_sync(0xFFFFFFFFu, maxr, off));
        mini = min(mini, __shfl_xor_sync(0xFFFFFFFFu, mini, off));
        maxi = max(maxi, __shfl_xor_sync(0xFFFFFFFFu, maxi, off));
    }
    if (lane == 0) {
        s_acc[warp]  = acc;
        s_minr[warp] = minr; s_maxr[warp] = maxr;
        s_mini[warp] = mini; s_maxi[warp] = maxi;
    }
    if (tid == 0) { s_last_row = false; s_last_all = false; }
    __syncthreads();

    if (tid == 0) {
        float a = 0.0f;
        int mr = INT_MAX, Mr = -1, mi = INT_MAX, Mi = -1;
        #pragma unroll
        for (int w = 0; w < BDIM / 32; w++) {
            a += s_acc[w];
            mr = min(mr, s_minr[w]); Mr = max(Mr, s_maxr[w]);
            mi = min(mi, s_mini[w]); Mi = max(Mi, s_maxi[w]);
        }
        g_unit[unit] = a;
        if (Mr >= 0) {
            atomicMax(&g_encfr[row], NSEG4 - mr);
            atomicMax(&g_enclr[row], Mr + 1);
        }
        if (Mi >= 0) {
            atomicMax(&g_encfi[row], NSEG4 - mi);
            atomicMax(&g_encli[row], Mi + 1);
        }
        __threadfence();                                   // publish unit + encs
        unsigned t = atomicAdd(&g_rowcnt[row], 1u);
        s_last_row = (t == (unsigned)(CHUNKS - 1));
    }
    __syncthreads();
    if (!s_last_row) return;

    // ======== last CTA of this row: exact bounds + correction ================
    if (tid == 0) {
        __threadfence();                                   // acquire
        int efr = g_encfr[row], elr = g_enclr[row];
        int efi = g_encfi[row], eli = g_encli[row];
        int fr = 0, lr = HALF - 1, fi = 0, li = HALF - 1;
        const float* Lr = lab + rb;
        const float* Lj = lab + rb + HALF;
        if (elr) {                                         // refine to element-exact
            int f = (NSEG4 - efr) * 4;
            while (fabsf(Lr[f]) <= THRESH) f++;
            int l = (elr - 1) * 4 + 3;
            while (fabsf(Lr[l]) <= THRESH) l--;
            fr = f; lr = l;
        }
        if (eli) {
            int f = (NSEG4 - efi) * 4;
            while (fabsf(Lj[f]) <= THRESH) f++;
            int l = (eli - 1) * 4 + 3;
            while (fabsf(Lj[l]) <= THRESH) l--;
            fi = f; li = l;
        }
        sh_fr = fr; sh_lr = lr; sh_fi = fi; sh_li = li;
        // reset per-row state for next graph replay
        g_encfr[row] = 0; g_enclr[row] = 0;
        g_encfi[row] = 0; g_encli[row] = 0;
        g_rowcnt[row] = 0;
    }
    __syncthreads();

    // correction: (P-1) * sum of squared diff outside [first,last] (tiny)
    float corr = 0.0f;
    {
        const float* Lr = lab  + rb;
        const float* Pr = pred + rb;
        const float* Lj = lab  + rb + HALF;
        const float* Pj = pred + rb + HALF;
        for (int j = tid; j < sh_fr; j += BDIM)            { float d = Pr[j] - Lr[j]; corr += d * d; }
        for (int j = sh_lr + 1 + tid; j < HALF; j += BDIM) { float d = Pr[j] - Lr[j]; corr += d * d; }
        for (int j = tid; j < sh_fi; j += BDIM)            { float d = Pj[j] - Lj[j]; corr += d * d; }
        for (int j = sh_li + 1 + tid; j < HALF; j += BDIM) { float d = Pj[j] - Lj[j]; corr += d * d; }
    }
    #pragma unroll
    for (int off = 16; off > 0; off >>= 1)
        corr += __shfl_xor_sync(0xFFFFFFFFu, corr, off);
    if (lane == 0) s_acc[warp] = corr;
    __syncthreads();

    if (tid == 0) {
        float c = 0.0f;
        #pragma unroll
        for (int w = 0; w < BDIM / 32; w++) c += s_acc[w];
        float rs = (PENALTY - 1.0f) * c;
        for (int u = 0; u < CHUNKS; u++)                    // fixed order: deterministic
            rs += g_unit[row * CHUNKS + u];
        g_rowsum[row] = rs;
        __threadfence();
        unsigned t = atomicAdd(&g_done, 1u);
        s_last_all = (t == (unsigned)(B - 1));
    }
    __syncthreads();
    if (!s_last_all) return;

    // ======== very last CTA: fold per-row sums, write output =================
    __threadfence();
    __shared__ float s_fin[256];
    s_fin[tid] = (tid < B) ? g_rowsum[tid] : 0.0f;
    __syncthreads();
    #pragma unroll
    for (int st = 128; st > 0; st >>= 1) {
        if (tid < st) s_fin[tid] += s_fin[tid + st];
        __syncthreads();
    }
    if (tid == 0) {
        out[0] = s_fin[0] / ((float)HALF * (float)B);
        g_done = 0;                                         // reset for replay
    }
}

extern "C" void kernel_launch(void* const* d_in, const int* in_sizes, int n_in,
                              void* d_out, int out_size)
{
    const float* pred = (const float*)d_in[0];
    const float* lab  = (const float*)d_in[1];
    float* out = (float*)d_out;

    const int B = in_sizes[0] / NCOL;   // 256

    loss_kernel<<<B * CHUNKS, BDIM>>>(pred, lab, out, B);
}